// round 14
// baseline (speedup 1.0000x reference)
#include <cuda_runtime.h>
#include <cuda_fp16.h>
#include <cstdint>
#include <math.h>

// Problem dims
#define B_  4
#define S_  1024
#define D_  512
#define H_  8
#define DK_ 64
#define FF_ 2048
#define L_  4
#define IN_ 768
#define NS_ 4
#define SD_ 64

#define BS  (B_*S_)            // 4096
#define BSD ((long long)BS*D_) // 2097152
#define NEG_INF __int_as_float(0xff800000)

// ---------------- scratch (device globals: allocation-free) ----------------
__device__ float g_pe[S_*D_];
__device__ float g_x[BS*D_];
__device__ float g_experts[NS_*BS*D_];
__device__ float g_summary[BS*D_];
__device__ float g_wgt[BS*4];
__device__ int   g_cnt[4];
__device__ int   g_list[4*BS];
// split fp16 buffers, layout [m][hi K | lo K]
__device__ __half g_qbf[25165824];    // q_raw' [4096][6144]
__device__ __half g_h1bf[25165824];   // h1'   [4][4096][1536] (compacted slots)
__device__ __half g_ybf[4194304];     // y'    [4096][1024]
__device__ __half g_xbf[4194304];     // x'    [4096][1024]
__device__ __half g_ctxbf[4194304];   // ctx'  [4096][1024]
__device__ __half g_ffnbf[16777216];  // ffn'  [4096][4096]
__device__ __half g_khh[2097152];     // K hi [32][1024][64]
__device__ __half g_khl[2097152];     // K lo
__device__ __half g_vth[8388608];     // Vt hi [4][32][64][1024]
// all weights, SINGLE fp16 [n][K]
__device__ __half g_wbf[17039360];

// weight buffer offsets (fp16 elements)
#define W_EXPW1 0LL
#define W_EXPW2 2359296LL
#define W_ADAPT 3932160LL
#define W_KW    5505024LL
#define W_VW    6553600LL
#define W_OW    7602176LL
#define W_FW1   8650752LL
#define W_FW2   12845056LL

// ================= PTX helpers ===============================================
__device__ __forceinline__ uint32_t smem_u32(const void* p) {
    uint32_t a;
    asm("{ .reg .u64 t; cvta.to.shared.u64 t, %1; cvt.u32.u64 %0, t; }" : "=r"(a) : "l"(p));
    return a;
}
__device__ __forceinline__ void cp_async16(uint32_t dst, const void* src) {
    asm volatile("cp.async.cg.shared.global [%0], [%1], 16;" :: "r"(dst), "l"(src));
}
#define CP_COMMIT() asm volatile("cp.async.commit_group;" ::: "memory")
#define CP_WAIT0()  asm volatile("cp.async.wait_group 0;" ::: "memory")
#define CP_WAIT1()  asm volatile("cp.async.wait_group 1;" ::: "memory")

__device__ __forceinline__ void ldsm_x4(uint32_t& r0, uint32_t& r1, uint32_t& r2,
                                        uint32_t& r3, uint32_t addr) {
    asm volatile("ldmatrix.sync.aligned.m8n8.x4.shared.b16 {%0,%1,%2,%3}, [%4];"
        : "=r"(r0), "=r"(r1), "=r"(r2), "=r"(r3) : "r"(addr));
}
__device__ __forceinline__ void mma16816(float* c, const uint32_t* a, const uint32_t* b) {
    asm volatile(
        "mma.sync.aligned.m16n8k16.row.col.f32.f16.f16.f32 "
        "{%0,%1,%2,%3}, {%4,%5,%6,%7}, {%8,%9}, {%0,%1,%2,%3};"
        : "+f"(c[0]), "+f"(c[1]), "+f"(c[2]), "+f"(c[3])
        : "r"(a[0]), "r"(a[1]), "r"(a[2]), "r"(a[3]), "r"(b[0]), "r"(b[1]));
}
__device__ __forceinline__ uint32_t pack_h2(float lo, float hi) {
    uint32_t d;
    asm("cvt.rn.f16x2.f32 %0, %1, %2;" : "=r"(d) : "f"(hi), "f"(lo));
    return d;
}
__device__ __forceinline__ float h2_lo(uint32_t p) {
    return __half2float(__ushort_as_half((unsigned short)(p & 0xffff)));
}
__device__ __forceinline__ float h2_hi(uint32_t p) {
    return __half2float(__ushort_as_half((unsigned short)(p >> 16)));
}

__device__ __forceinline__ uint32_t swz(uint32_t base, int r, int ch) {
    return base + r * 128 + ((ch ^ (r & 7)) << 4);
}

// ================= conversions ==============================================
// q_raw [4096][3072] fp32 -> q' [4096][6144] = [hi 3072 | lo 3072]
__global__ __launch_bounds__(256) void conv_qraw_kernel(
    const float* __restrict__ src, __half* __restrict__ dst)
{
    int idx = blockIdx.x * 256 + threadIdx.x;
    int m = idx / 768;
    int k = (idx - m * 768) * 4;
    float4 v = *(const float4*)(src + (long long)m * 3072 + k);
    unsigned short hb[4], lb[4];
    float vv[4] = {v.x, v.y, v.z, v.w};
    #pragma unroll
    for (int i = 0; i < 4; i++) {
        __half h = __float2half_rn(vv[i]);
        __half l = __float2half_rn(vv[i] - __half2float(h));
        hb[i] = __half_as_ushort(h);
        lb[i] = __half_as_ushort(l);
    }
    long long base = (long long)m * 6144;
    *(uint2*)(dst + base + k) = make_uint2((uint32_t)hb[0] | ((uint32_t)hb[1] << 16),
                                           (uint32_t)hb[2] | ((uint32_t)hb[3] << 16));
    *(uint2*)(dst + base + 3072 + k) = make_uint2((uint32_t)lb[0] | ((uint32_t)lb[1] << 16),
                                                  (uint32_t)lb[2] | ((uint32_t)lb[3] << 16));
}

// all weights W [z][K][N] fp32 -> W' [z][n][K] single fp16, one launch
struct ConvSegs {
    const float* src[8];
    long long dstOff[8];
    int K[8], N[8], tOff[8];
};

__global__ void convB_all_kernel(ConvSegs segs, __half* __restrict__ wb)
{
    __shared__ float t[32][33];
    int bx = blockIdx.x;
    int seg = 0;
    #pragma unroll
    for (int i = 7; i >= 1; i--) if (bx >= segs.tOff[i]) { seg = i; break; }
    const int K = segs.K[seg], N = segs.N[seg];
    int tl = bx - segs.tOff[seg];
    int tz = (K >> 5) * (N >> 5);
    int z = tl / tz, rr = tl - z * tz;
    int k0 = (rr % (K >> 5)) * 32, n0 = (rr / (K >> 5)) * 32;
    const float* s = segs.src[seg] + (long long)z * K * N;
    __half* dstz = wb + segs.dstOff[seg] + (long long)z * N * K;
    int tx = threadIdx.x, ty = threadIdx.y;
    #pragma unroll
    for (int r = ty; r < 32; r += 8)
        t[r][tx] = s[(long long)(k0 + r) * N + n0 + tx];
    __syncthreads();
    #pragma unroll
    for (int r = ty; r < 32; r += 8) {
        dstz[(long long)(n0 + r) * K + k0 + tx] = __float2half_rn(t[tx][r]);
    }
}

// ================= unified split GEMM (fp16, 2 terms: Xh*W + Xl*W) ==========
// 128 threads, 4 warps, warp tile 32x64 over 128x64 CTA tile, 2-stage, 2 CTA/SM.
// gmode: 0 = dense, 1 = gather-A rows via list (Sp at slots), 2 = scatter-C rows
#define G2_STAGE 40960
#define G2_SMEM  81920

__global__ __launch_bounds__(128, 2) void gemm2_kernel(
    const __half* __restrict__ Ah0, int loA, int ldA, long long zA,
    const __half* __restrict__ Bt0, long long zB, int K,
    const float* __restrict__ bias, int sBias,
    const float* __restrict__ res,
    float* __restrict__ C, long long sC,
    __half* __restrict__ Sp, long long zSp,
    __half* __restrict__ KH, __half* __restrict__ KL,
    __half* __restrict__ VH,
    const int* __restrict__ glist, const int* __restrict__ gcnt,
    int gmode, int N, int relu)
{
    extern __shared__ __align__(1024) char smem[];
    __shared__ int slist[128];
    const int tid = threadIdx.x, wid = tid >> 5, lane = tid & 31;
    const int wy = wid;                          // 4 warps stacked in M, 32x64 each
    const int z = blockIdx.z;
    const int brow = blockIdx.y * 128, bcol = blockIdx.x * 64;

    int cnt = 0;
    if (gmode) {
        cnt = gcnt[z];
        if (brow >= cnt) return;
        int i = brow + tid;
        slist[tid] = glist[z * BS + (i < cnt ? i : cnt - 1)];
    }

    const __half* Ahz = Ah0 + (long long)z * zA;
    const __half* Bh = Bt0 + (long long)z * zB + (long long)bcol * K;
    if (bias) bias += (long long)z * sBias;
    if (C) C += (long long)z * sC;
    if (Sp) Sp += (long long)z * zSp;

    if (gmode) __syncthreads();

    const uint32_t sb = smem_u32(smem);
    const int NC = K >> 6;

    // stage layout: Ah 16K @0, Al 16K @16384, B 8K @32768 (40K total)
    auto load_tile = [&](int c, int s) {
        const int kc = c * 64;
        const uint32_t st = sb + s * G2_STAGE;
        #pragma unroll
        for (int i = 0; i < 20; i++) {
            int idx = tid + i * 128;          // 0..2559
            if (idx < 1024) {
                int r = idx >> 3, ch = idx & 7;
                int rowA = (gmode == 1) ? slist[r] : (brow + r);
                cp_async16(swz(st, r, ch),
                           (const char*)(Ahz + (long long)rowA * ldA + kc) + ch * 16);
            } else if (idx < 2048) {
                int j = idx - 1024;
                int r = j >> 3, ch = j & 7;
                int rowA = (gmode == 1) ? slist[r] : (brow + r);
                cp_async16(swz(st + 16384, r, ch),
                           (const char*)(Ahz + loA + (long long)rowA * ldA + kc) + ch * 16);
            } else {
                int j = idx - 2048;
                int r = j >> 3, ch = j & 7;
                cp_async16(swz(st + 32768, r, ch),
                           (const char*)(Bh + (long long)r * K + kc) + ch * 16);
            }
        }
        CP_COMMIT();
    };

    float acc[2][8][4] = {};
    load_tile(0, 0);
    load_tile(1, 1);

    for (int c = 0; c < NC; c++) {
        const int s = c & 1;
        if (c + 1 < NC) { CP_WAIT1(); } else { CP_WAIT0(); }
        __syncthreads();
        const uint32_t stA = sb + s * G2_STAGE;

        #pragma unroll
        for (int ks = 0; ks < 4; ks++) {
            const int cb = ks * 2;
            uint32_t ah[2][4], al[2][4];
            #pragma unroll
            for (int ms = 0; ms < 2; ms++) {
                int r = wy * 32 + ms * 16 + (lane & 15);
                int ch = cb + (lane >> 4);
                ldsm_x4(ah[ms][0], ah[ms][1], ah[ms][2], ah[ms][3], swz(stA, r, ch));
                ldsm_x4(al[ms][0], al[ms][1], al[ms][2], al[ms][3], swz(stA + 16384, r, ch));
            }
            uint32_t bh[8][2];
            #pragma unroll
            for (int nh = 0; nh < 4; nh++) {
                int g = lane >> 3;
                int r = nh * 16 + ((g & 2) << 2) + (lane & 7);
                int ch = cb + (g & 1);
                uint32_t r0, r1, r2, r3;
                ldsm_x4(r0, r1, r2, r3, swz(stA + 32768, r, ch));
                bh[nh*2][0] = r0; bh[nh*2][1] = r1;
                bh[nh*2+1][0] = r2; bh[nh*2+1][1] = r3;
            }
            // term-major: 16 independent accumulators between reuses
            #pragma unroll
            for (int ms = 0; ms < 2; ms++)
                #pragma unroll
                for (int ns = 0; ns < 8; ns++)
                    mma16816(acc[ms][ns], ah[ms], bh[ns]);
            #pragma unroll
            for (int ms = 0; ms < 2; ms++)
                #pragma unroll
                for (int ns = 0; ns < 8; ns++)
                    mma16816(acc[ms][ns], al[ms], bh[ns]);
        }
        __syncthreads();
        if (c + 2 < NC) load_tile(c + 2, s);
    }

    // ---- epilogue ----
    const int qrow = lane >> 2, qcol = (lane & 3) * 2;
    #pragma unroll
    for (int ms = 0; ms < 2; ms++) {
        int m = brow + wy * 32 + ms * 16 + qrow;
        bool ok0 = !gmode || (m < cnt);
        bool ok1 = !gmode || (m + 8 < cnt);
        int crow0 = (gmode == 2 && ok0) ? slist[m - brow] : m;
        int crow1 = (gmode == 2 && ok1) ? slist[m + 8 - brow] : m + 8;
        #pragma unroll
        for (int ns = 0; ns < 8; ns++) {
            int n = bcol + ns * 8 + qcol;
            float2 v0 = make_float2(acc[ms][ns][0], acc[ms][ns][1]);
            float2 v1 = make_float2(acc[ms][ns][2], acc[ms][ns][3]);
            if (bias) {
                float b0 = bias[n], b1 = bias[n + 1];
                v0.x += b0; v0.y += b1; v1.x += b0; v1.y += b1;
            }
            if (res) {
                float2 r0 = *(const float2*)(res + (long long)m * N + n);
                float2 r1 = *(const float2*)(res + (long long)(m + 8) * N + n);
                v0.x += r0.x; v0.y += r0.y; v1.x += r1.x; v1.y += r1.y;
            }
            if (relu) {
                v0.x = fmaxf(v0.x, 0.f); v0.y = fmaxf(v0.y, 0.f);
                v1.x = fmaxf(v1.x, 0.f); v1.y = fmaxf(v1.y, 0.f);
            }
            if (C) {
                if (ok0) *(float2*)(C + (long long)crow0 * N + n) = v0;
                if (ok1) *(float2*)(C + (long long)crow1 * N + n) = v1;
            }
            uint32_t hp0 = pack_h2(v0.x, v0.y);
            uint32_t hp1 = pack_h2(v1.x, v1.y);
            uint32_t lp0 = pack_h2(v0.x - h2_lo(hp0), v0.y - h2_hi(hp0));
            uint32_t lp1 = pack_h2(v1.x - h2_lo(hp1), v1.y - h2_hi(hp1));
            if (Sp) {
                long long r0 = (long long)m * 2 * N, r1 = (long long)(m + 8) * 2 * N;
                if (ok0) {
                    *(uint32_t*)(Sp + r0 + n)     = hp0;
                    *(uint32_t*)(Sp + r0 + N + n) = lp0;
                }
                if (ok1) {
                    *(uint32_t*)(Sp + r1 + n)     = hp1;
                    *(uint32_t*)(Sp + r1 + N + n) = lp1;
                }
            }
            if (KH) {
                long long a0 = (((long long)((m >> 10) * 8 + (n >> 6))) * 1024 + (m & 1023)) * 64 + (n & 63);
                long long a1 = a0 + 8LL * 64;
                *(uint32_t*)(KH + a0) = hp0;  *(uint32_t*)(KL + a0) = lp0;
                *(uint32_t*)(KH + a1) = hp1;  *(uint32_t*)(KL + a1) = lp1;
            }
            if (VH) {
                int b = m >> 10, h = n >> 6, d = n & 63, si = m & 1023;
                long long base = (((long long)(z * 32 + b * 8 + h)) * 64 + d) * 1024 + si;
                unsigned short* vh = (unsigned short*)VH;
                vh[base]            = (unsigned short)(hp0 & 0xffff);
                vh[base + 1024]     = (unsigned short)(hp0 >> 16);
                vh[base + 8]        = (unsigned short)(hp1 & 0xffff);
                vh[base + 1024 + 8] = (unsigned short)(hp1 >> 16);
            }
        }
    }
}

// ================= tensor-core flash attention (fp16 2-term) =================
// smem: Qhi @0 (8K), Qlo @8192; stages @16384 + s*16384: {Khi 8K, Vhi 8K}
#define ATTN_SMEM 49152

__global__ __launch_bounds__(128) void attn_mma_kernel(
    const __half* __restrict__ khh, const __half* __restrict__ khl,
    const __half* __restrict__ vth,
    __half* __restrict__ Cx)
{
    extern __shared__ __align__(1024) char smem[];
    const uint32_t sb = smem_u32(smem);
    const int tid = threadIdx.x, wid = tid >> 5, lane = tid & 31;
    const int qb = 15 - blockIdx.x;
    const int bh = blockIdx.y;
    const int q0 = qb * 64;

    const __half* Kh = khh + (long long)bh * S_ * 64;
    const __half* Kl = khl + (long long)bh * S_ * 64;
    const __half* Vh = vth + (long long)bh * 64 * S_;

    auto load_kv = [&](int jt, int s) {
        const int j0 = jt * 64;
        const uint32_t base = sb + 16384 + s * 16384;
        #pragma unroll
        for (int i = 0; i < 4; i++) {
            int idx = tid + i * 128;
            int r = idx >> 3, ch = idx & 7;
            cp_async16(swz(base, r, ch),
                       (const char*)(Kh + (long long)(j0 + r) * 64) + ch * 16);
            cp_async16(swz(base + 8192, r, ch),
                       (const char*)(Vh + (long long)r * S_ + j0) + ch * 16);
        }
        CP_COMMIT();
    };

    #pragma unroll
    for (int i = 0; i < 4; i++) {
        int idx = tid + i * 128;
        int r = idx >> 3, ch = idx & 7;
        cp_async16(swz(sb, r, ch),
                   (const char*)(Kh + (long long)(q0 + r) * 64) + ch * 16);
        cp_async16(swz(sb + 8192, r, ch),
                   (const char*)(Kl + (long long)(q0 + r) * 64) + ch * 16);
    }
    load_kv(0, 0);
    CP_WAIT0();
    __syncthreads();

    uint32_t qh[4][4], ql[4][4];
    #pragma unroll
    for (int ks = 0; ks < 4; ks++) {
        int r = wid * 16 + (lane & 15);
        int ch = 2 * ks + (lane >> 4);
        ldsm_x4(qh[ks][0], qh[ks][1], qh[ks][2], qh[ks][3], swz(sb, r, ch));
        ldsm_x4(ql[ks][0], ql[ks][1], ql[ks][2], ql[ks][3], swz(sb + 8192, r, ch));
    }

    float ctx[8][4] = {};
    float m0 = NEG_INF, m1 = NEG_INF, l0 = 0.f, l1 = 0.f;
    const int rg0 = q0 + wid * 16 + (lane >> 2);

    for (int jt = 0; jt <= qb; jt++) {
        const int s = jt & 1;
        if (jt < qb) { load_kv(jt + 1, s ^ 1); CP_WAIT1(); }
        else if (jt > 0) { CP_WAIT0(); }
        __syncthreads();

        const uint32_t bK = sb + 16384 + s * 16384;

        float sc[8][4] = {};
        #pragma unroll
        for (int ks = 0; ks < 4; ks++) {
            uint32_t bh_[8][2];
            #pragma unroll
            for (int ng = 0; ng < 4; ng++) {
                int g = lane >> 3;
                int r = ng * 16 + ((g & 2) << 2) + (lane & 7);
                int ch = 2 * ks + (g & 1);
                uint32_t a0, a1, a2, a3;
                ldsm_x4(a0, a1, a2, a3, swz(bK, r, ch));
                bh_[2*ng][0] = a0; bh_[2*ng][1] = a1;
                bh_[2*ng+1][0] = a2; bh_[2*ng+1][1] = a3;
            }
            #pragma unroll
            for (int nt = 0; nt < 8; nt++) {
                mma16816(sc[nt], qh[ks], bh_[nt]);
                mma16816(sc[nt], ql[ks], bh_[nt]);
            }
        }

        const int j0 = jt * 64;
        const bool diag = (jt == qb);
        const int cb0 = j0 + (lane & 3) * 2;
        float rm0 = NEG_INF, rm1 = NEG_INF;
        #pragma unroll
        for (int nt = 0; nt < 8; nt++) {
            int c0 = cb0 + nt * 8, c1 = c0 + 1;
            float s0 = sc[nt][0] * 0.125f, s1 = sc[nt][1] * 0.125f;
            float s2 = sc[nt][2] * 0.125f, s3 = sc[nt][3] * 0.125f;
            if (diag) {
                if (c0 >= rg0)     s0 = NEG_INF;
                if (c1 >= rg0)     s1 = NEG_INF;
                if (c0 >= rg0 + 8) s2 = NEG_INF;
                if (c1 >= rg0 + 8) s3 = NEG_INF;
            }
            sc[nt][0] = s0; sc[nt][1] = s1; sc[nt][2] = s2; sc[nt][3] = s3;
            rm0 = fmaxf(rm0, fmaxf(s0, s1));
            rm1 = fmaxf(rm1, fmaxf(s2, s3));
        }
        #pragma unroll
        for (int o = 1; o <= 2; o <<= 1) {
            rm0 = fmaxf(rm0, __shfl_xor_sync(0xffffffffu, rm0, o));
            rm1 = fmaxf(rm1, __shfl_xor_sync(0xffffffffu, rm1, o));
        }
        float mn0 = fmaxf(m0, rm0), mn1 = fmaxf(m1, rm1);
        float ms0 = (mn0 == NEG_INF) ? 0.f : mn0;
        float ms1 = (mn1 == NEG_INF) ? 0.f : mn1;
        float cr0 = __expf(m0 - ms0), cr1 = __expf(m1 - ms1);
        float rs0 = 0.f, rs1 = 0.f;
        #pragma unroll
        for (int nt = 0; nt < 8; nt++) {
            sc[nt][0] = __expf(sc[nt][0] - ms0); rs0 += sc[nt][0];
            sc[nt][1] = __expf(sc[nt][1] - ms0); rs0 += sc[nt][1];
            sc[nt][2] = __expf(sc[nt][2] - ms1); rs1 += sc[nt][2];
            sc[nt][3] = __expf(sc[nt][3] - ms1); rs1 += sc[nt][3];
        }
        #pragma unroll
        for (int o = 1; o <= 2; o <<= 1) {
            rs0 += __shfl_xor_sync(0xffffffffu, rs0, o);
            rs1 += __shfl_xor_sync(0xffffffffu, rs1, o);
        }
        l0 = l0 * cr0 + rs0; l1 = l1 * cr1 + rs1;
        m0 = mn0; m1 = mn1;
        #pragma unroll
        for (int nt = 0; nt < 8; nt++) {
            ctx[nt][0] *= cr0; ctx[nt][1] *= cr0;
            ctx[nt][2] *= cr1; ctx[nt][3] *= cr1;
        }

        uint32_t ph[4][4], pl[4][4];
        #pragma unroll
        for (int kj = 0; kj < 4; kj++) {
            const int t0 = 2 * kj, t1 = 2 * kj + 1;
            ph[kj][0] = pack_h2(sc[t0][0], sc[t0][1]);
            ph[kj][1] = pack_h2(sc[t0][2], sc[t0][3]);
            ph[kj][2] = pack_h2(sc[t1][0], sc[t1][1]);
            ph[kj][3] = pack_h2(sc[t1][2], sc[t1][3]);
            pl[kj][0] = pack_h2(sc[t0][0] - h2_lo(ph[kj][0]), sc[t0][1] - h2_hi(ph[kj][0]));
            pl[kj][1] = pack_h2(sc[t0][2] - h2_lo(ph[kj][1]), sc[t0][3] - h2_hi(ph[kj][1]));
            pl[kj][2] = pack_h2(sc[t1][0] - h2_lo(ph[kj][2]), sc[t1][1] - h2_hi(ph[kj][2]));
            pl[kj][3] = pack_h2(sc[t1][2] - h2_lo(ph[kj][3]), sc[t1][3] - h2_hi(ph[kj][3]));
        }

        const uint32_t bV = bK + 8192;
        #pragma unroll
        for (int kj = 0; kj < 4; kj++) {
            uint32_t vh_[8][2];
            #pragma unroll
            for (int dg = 0; dg < 4; dg++) {
                int g = lane >> 3;
                int r = dg * 16 + ((g & 2) << 2) + (lane & 7);
                int ch = 2 * kj + (g & 1);
                uint32_t a0, a1, a2, a3;
                ldsm_x4(a0, a1, a2, a3, swz(bV, r, ch));
                vh_[2*dg][0] = a0; vh_[2*dg][1] = a1;
                vh_[2*dg+1][0] = a2; vh_[2*dg+1][1] = a3;
            }
            #pragma unroll
            for (int nt = 0; nt < 8; nt++) {
                mma16816(ctx[nt], ph[kj], vh_[nt]);
                mma16816(ctx[nt], pl[kj], vh_[nt]);
            }
        }
        __syncthreads();
    }

    float inv0 = (l0 > 0.f) ? 1.f / l0 : 0.f;
    float inv1 = (l1 > 0.f) ? 1.f / l1 : 0.f;
    const int b = bh >> 3, h = bh & 7;
    const int row0 = b * S_ + q0 + wid * 16 + (lane >> 2);
    const int colb = h * 64 + (lane & 3) * 2;
    #pragma unroll
    for (int nt = 0; nt < 8; nt++) {
        float a0 = ctx[nt][0] * inv0, a1 = ctx[nt][1] * inv0;
        float a2 = ctx[nt][2] * inv1, a3 = ctx[nt][3] * inv1;
        uint32_t hp0 = pack_h2(a0, a1);
        uint32_t hp1 = pack_h2(a2, a3);
        uint32_t lp0 = pack_h2(a0 - h2_lo(hp0), a1 - h2_hi(hp0));
        uint32_t lp1 = pack_h2(a2 - h2_lo(hp1), a3 - h2_hi(hp1));
        long long r0 = (long long)row0 * 1024, r1 = (long long)(row0 + 8) * 1024;
        int cc = colb + nt * 8;
        *(uint32_t*)(Cx + r0 + cc)       = hp0;
        *(uint32_t*)(Cx + r0 + 512 + cc) = lp0;
        *(uint32_t*)(Cx + r1 + cc)       = hp1;
        *(uint32_t*)(Cx + r1 + 512 + cc) = lp1;
    }
}

// ---------------- positional embedding (also zero gate counters) -----------
__global__ void pe_kernel(float* __restrict__ pe) {
    if (blockIdx.x == 0 && threadIdx.x < 4) g_cnt[threadIdx.x] = 0;
    int s = blockIdx.x;
    int j = threadIdx.x;
    float div = expf((float)(2*j) * (-9.210340371976184f / (float)D_));
    float arg = (float)s * div;
    pe[s*D_ + 2*j]     = sinf(arg);
    pe[s*D_ + 2*j + 1] = cosf(arg);
}

__global__ __launch_bounds__(256) void add_pe_kernel(
    const float* __restrict__ qa, const float* __restrict__ pe,
    __half* __restrict__ yb)
{
    int i = blockIdx.x * 256 + threadIdx.x;
    float v = qa[i] + pe[i & (S_*D_ - 1)];
    int m = i >> 9, c = i & 511;
    __half h = __float2half_rn(v);
    yb[(long long)m * 1024 + c]       = h;
    yb[(long long)m * 1024 + 512 + c] = __float2half_rn(v - __half2float(h));
}

// ---------------- gate: logits -> top-2 weights + expert row lists ----------
__global__ __launch_bounds__(256) void gate_kernel(
    const float* __restrict__ summary, const float* __restrict__ m_seq,
    const float* __restrict__ gate_w,  const float* __restrict__ gate_b,
    float* __restrict__ wgt, int* __restrict__ cnt, int* __restrict__ list)
{
    __shared__ float red[4][8];
    const int row = blockIdx.x;
    const int tid = threadIdx.x;

    float p0 = 0, p1 = 0, p2 = 0, p3 = 0;
    for (int e = tid; e < D_ + SD_; e += 256) {
        float xv = (e < D_) ? summary[(long long)row * D_ + e]
                            : m_seq[(long long)row * SD_ + (e - D_)];
        float4 w = *(const float4*)(gate_w + e * 4);
        p0 += xv * w.x; p1 += xv * w.y; p2 += xv * w.z; p3 += xv * w.w;
    }
    #pragma unroll
    for (int o = 16; o > 0; o >>= 1) {
        p0 += __shfl_xor_sync(0xffffffffu, p0, o);
        p1 += __shfl_xor_sync(0xffffffffu, p1, o);
        p2 += __shfl_xor_sync(0xffffffffu, p2, o);
        p3 += __shfl_xor_sync(0xffffffffu, p3, o);
    }
    if ((tid & 31) == 0) {
        int w = tid >> 5;
        red[0][w] = p0; red[1][w] = p1; red[2][w] = p2; red[3][w] = p3;
    }
    __syncthreads();

    if (tid == 0) {
        float l[4];
        #pragma unroll
        for (int j = 0; j < 4; j++) {
            float t = gate_b[j];
            #pragma unroll
            for (int w = 0; w < 8; w++) t += red[j][w];
            l[j] = t;
        }
        float m1v = -INFINITY, m2v = -INFINITY;
        #pragma unroll
        for (int j = 0; j < 4; j++) {
            if (l[j] > m1v) { m2v = m1v; m1v = l[j]; }
            else if (l[j] > m2v) { m2v = l[j]; }
        }
        float sum = 0.f, e4[4];
        #pragma unroll
        for (int j = 0; j < 4; j++) {
            e4[j] = (l[j] >= m2v) ? __expf(l[j] - m1v) : 0.f;
            sum += e4[j];
        }
        #pragma unroll
        for (int j = 0; j < 4; j++) {
            wgt[row * 4 + j] = e4[j] / sum;
            if (l[j] >= m2v) {
                int p = atomicAdd(&cnt[j], 1);
                list[j * BS + p] = row;
            }
        }
    }
}

// ---------------- MoE combine + LN + PE -> x (fp32 + split) ----------------
__global__ __launch_bounds__(256) void moe_kernel(
    const float* __restrict__ wgt, const float* __restrict__ experts,
    const float* __restrict__ lng, const float* __restrict__ lnb,
    const float* __restrict__ pe, float* __restrict__ x,
    __half* __restrict__ xb)
{
    __shared__ float r1[8], r2[8];
    const int row = blockIdx.x;
    const int tid = threadIdx.x;
    const int s_idx = row & (S_ - 1);

    const float w0 = wgt[row*4], w1 = wgt[row*4+1], w2 = wgt[row*4+2], w3 = wgt[row*4+3];
    const long long base = (long long)row * D_;
    const int t2 = tid + 256;
    float c0 = w0 * experts[0*BSD + base + tid] + w1 * experts[1*BSD + base + tid]
             + w2 * experts[2*BSD + base + tid] + w3 * experts[3*BSD + base + tid];
    float c1 = w0 * experts[0*BSD + base + t2]  + w1 * experts[1*BSD + base + t2]
             + w2 * experts[2*BSD + base + t2]  + w3 * experts[3*BSD + base + t2];

    float s = c0 + c1, q = c0 * c0 + c1 * c1;
    #pragma unroll
    for (int o = 16; o > 0; o >>= 1) {
        s += __shfl_xor_sync(0xffffffffu, s, o);
        q += __shfl_xor_sync(0xffffffffu, q, o);
    }
    if ((tid & 31) == 0) { r1[tid >> 5] = s; r2[tid >> 5] = q; }
    __syncthreads();
    float ts = 0, tq = 0;
    #pragma unroll
    for (int w = 0; w < 8; w++) { ts += r1[w]; tq += r2[w]; }
    float mu = ts * (1.f / 512.f);
    float var = tq * (1.f / 512.f) - mu * mu;
    float rstd = rsqrtf(var + 1e-5f);

    float o0 = (c0 - mu) * rstd * lng[tid] + lnb[tid] + pe[s_idx * D_ + tid];
    float o1 = (c1 - mu) * rstd * lng[t2]  + lnb[t2]  + pe[s_idx * D_ + t2];
    x[base + tid] = o0;
    x[base + t2]  = o1;
    long long b2 = (long long)row * 1024;
    __half h0 = __float2half_rn(o0);
    __half h1 = __float2half_rn(o1);
    xb[b2 + tid]        = h0;
    xb[b2 + t2]         = h1;
    xb[b2 + 512 + tid]  = __float2half_rn(o0 - __half2float(h0));
    xb[b2 + 512 + t2]   = __float2half_rn(o1 - __half2float(h1));
}

// ---------------- LayerNorm (fp32 out + optional split) --------------------
__global__ __launch_bounds__(256) void ln_kernel(
    const float* __restrict__ in, const float* __restrict__ g,
    const float* __restrict__ b, float* __restrict__ out,
    __half* __restrict__ sp)
{
    __shared__ float r1[8], r2[8];
    const int row = blockIdx.x, tid = threadIdx.x;
    const long long base = (long long)row * D_;
    float v0 = in[base + tid], v1 = in[base + tid + 256];
    float s = v0 + v1, q = v0 * v0 + v1 * v1;
    #pragma unroll
    for (int o = 16; o > 0; o >>= 1) {
        s += __shfl_xor_sync(0xffffffffu, s, o);
        q += __shfl_xor_sync(0xffffffffu, q, o);
    }
    if ((tid & 31) == 0) { r1[tid >> 5] = s; r2[tid >> 5] = q; }
    __syncthreads();
    float ts = 0, tq = 0;
    #pragma unroll
    for (int w = 0; w < 8; w++) { ts += r1[w]; tq += r2[w]; }
    float mu = ts * (1.f / 512.f);
    float var = tq * (1.f / 512.f) - mu * mu;
    float rstd = rsqrtf(var + 1e-5f);
    float o0 = (v0 - mu) * rstd * g[tid]       + b[tid];
    float o1 = (v1 - mu) * rstd * g[tid + 256] + b[tid + 256];
    out[base + tid]       = o0;
    out[base + tid + 256] = o1;
    if (sp) {
        long long b2 = (long long)row * 1024;
        __half h0 = __float2half_rn(o0);
        __half h1 = __float2half_rn(o1);
        sp[b2 + tid]       = h0;
        sp[b2 + tid + 256] = h1;
        sp[b2 + 512 + tid]       = __float2half_rn(o0 - __half2float(h0));
        sp[b2 + 512 + tid + 256] = __float2half_rn(o1 - __half2float(h1));
    }
}

// ================= host wrapper ==============================================
typedef __half h16;

static void gemmS(cudaStream_t st,
                  const h16* Ah, int loA, int ldA, long long zA,
                  const h16* Bt, long long zB, int K,
                  const float* bias, int sBias, const float* res,
                  float* C, long long sC, h16* Sp, long long zSp,
                  h16* KH, h16* KL, h16* VH,
                  const int* glist, const int* gcnt, int gmode,
                  int N, int nz, int relu)
{
    gemm2_kernel<<<dim3(N/64, 32, nz), 128, G2_SMEM, st>>>(
        Ah, loA, ldA, zA, Bt, zB, K, bias, sBias, res, C, sC,
        Sp, zSp, KH, KL, VH, glist, gcnt, gmode, N, relu);
}

extern "C" void kernel_launch(void* const* d_in, const int* in_sizes, int n_in,
                              void* d_out, int out_size)
{
    const float* q_raw   = (const float*)d_in[0];
    const float* m_seq   = (const float*)d_in[1];
    const float* qa      = (const float*)d_in[2];
    const float* exp_w1  = (const float*)d_in[3];
    const float* exp_b1  = (const float*)d_in[4];
    const float* exp_w2  = (const float*)d_in[5];
    const float* exp_b2  = (const float*)d_in[6];
    const float* adapt_w = (const float*)d_in[7];
    const float* adapt_b = (const float*)d_in[8];
    const float* gate_w  = (const float*)d_in[9];
    const float* gate_b  = (const float*)d_in[10];
    const float* moe_g   = (const float*)d_in[11];
    const float* moe_b   = (const float*)d_in[12];
    const float* kw      = (const float*)d_in[13];
    const float* kb      = (const float*)d_in[14];
    const float* vw      = (const float*)d_in[15];
    const float* vb      = (const float*)d_in[16];
    const float* ow      = (const float*)d_in[17];
    const float* ob      = (const float*)d_in[18];
    const float* ln1g    = (const float*)d_in[19];
    const float* ln1b    = (const float*)d_in[20];
    const float* fw1     = (const float*)d_in[21];
    const float* fb1     = (const float*)d_in[22];
    const float* fw2     = (const float*)d_in[23];
    const float* fb2     = (const float*)d_in[24];
    const float* ln2g    = (const float*)d_in[25];
    const float* ln2b    = (const float*)d_in[26];

    float *pe, *x, *experts, *summary, *wgtp;
    int *cntp, *listp;
    h16 *qbf, *h1bf, *ybf, *xbf, *ctxbf, *ffnbf, *wbf, *khh, *khl, *vth;
    cudaGetSymbolAddress((void**)&pe, g_pe);
    cudaGetSymbolAddress((void**)&x, g_x);
    cudaGetSymbolAddress((void**)&experts, g_experts);
    cudaGetSymbolAddress((void**)&summary, g_summary);
    cudaGetSymbolAddress((void**)&wgtp, g_wgt);
    cudaGetSymbolAddress((void**)&cntp, g_cnt);
    cudaGetSymbolAddress((void**)&listp, g_list);
    cudaGetSymbolAddress((void**)&qbf, g_qbf);
    cudaGetSymbolAddress((void**)&h1bf, g_h1bf);
    cudaGetSymbolAddress((void**)&ybf, g_ybf);
    cudaGetSymbolAddress((void**)&xbf, g_xbf);
    cudaGetSymbolAddress((void**)&ctxbf, g_ctxbf);
    cudaGetSymbolAddress((void**)&ffnbf, g_ffnbf);
    cudaGetSymbolAddress((void**)&wbf, g_wbf);
    cudaGetSymbolAddress((void**)&khh, g_khh);
    cudaGetSymbolAddress((void**)&khl, g_khl);
    cudaGetSymbolAddress((void**)&vth, g_vth);

    static int attr_set = 0;
    static cudaStream_t s2;
    static cudaEvent_t evFork, evJoin;
    if (!attr_set) {
        cudaFuncSetAttribute(gemm2_kernel,
                             cudaFuncAttributeMaxDynamicSharedMemorySize, G2_SMEM);
        cudaFuncSetAttribute(attn_mma_kernel,
                             cudaFuncAttributeMaxDynamicSharedMemorySize, ATTN_SMEM);
        cudaStreamCreateWithFlags(&s2, cudaStreamNonBlocking);
        cudaEventCreateWithFlags(&evFork, cudaEventDisableTiming);
        cudaEventCreateWithFlags(&evJoin, cudaEventDisableTiming);
        attr_set = 1;
    }
    cudaStream_t s0 = 0;

    // --- stream 0: shared prologue ---
    pe_kernel<<<S_, 256, 0, s0>>>(pe);
    conv_qraw_kernel<<<4096 * 768 / 256, 256, 0, s0>>>(q_raw, qbf);
    {
        ConvSegs cs;
        cs.src[0] = exp_w1;  cs.dstOff[0] = W_EXPW1; cs.K[0] = 768;  cs.N[0] = 768;  cs.tOff[0] = 0;
        cs.src[1] = exp_w2;  cs.dstOff[1] = W_EXPW2; cs.K[1] = 768;  cs.N[1] = 512;  cs.tOff[1] = 2304;
        cs.src[2] = adapt_w; cs.dstOff[2] = W_ADAPT; cs.K[2] = 3072; cs.N[2] = 512;  cs.tOff[2] = 3840;
        cs.src[3] = kw;      cs.dstOff[3] = W_KW;    cs.K[3] = 512;  cs.N[3] = 512;  cs.tOff[3] = 5376;
        cs.src[4] = vw;      cs.dstOff[4] = W_VW;    cs.K[4] = 512;  cs.N[4] = 512;  cs.tOff[4] = 6400;
        cs.src[5] = ow;      cs.dstOff[5] = W_OW;    cs.K[5] = 512;  cs.N[5] = 512;  cs.tOff[5] = 7424;
        cs.src[6] = fw1;     cs.dstOff[6] = W_FW1;   cs.K[6] = 512;  cs.N[6] = 2048; cs.tOff[6] = 8448;
        cs.src[7] = fw2;     cs.dstOff[7] = W_FW2;   cs.K[7] = 2048; cs.N[7] = 512;  cs.tOff[7] = 12544;
        convB_all_kernel<<<16640, dim3(32, 8), 0, s0>>>(cs, wbf);
    }

    // --- fork: stream 2 runs the V chain while stream 0 runs the MoE chain ---
    cudaEventRecord(evFork, s0);
    cudaStreamWaitEvent(s2, evFork, 0);

    // stream 2: y' = qa + pe, then V for all layers -> transposed fp16
    add_pe_kernel<<<(int)(BSD / 256), 256, 0, s2>>>(qa, pe, ybf);
    gemmS(s2, ybf, 512, 1024, 0, wbf + W_VW, 512LL*512, 512, vb, D_, nullptr,
          nullptr, 0, nullptr, 0, nullptr, nullptr, vth,
          nullptr, nullptr, 0, 512, L_, 0);
    cudaEventRecord(evJoin, s2);

    // stream 0: MoE chain
    gemmS(s0, qbf, 3072, 6144, 0, wbf + W_ADAPT, 0, 3072, adapt_b, 0, nullptr,
          summary, 0, nullptr, 0, nullptr, nullptr, nullptr,
          nullptr, nullptr, 0, 512, 1, 1);
    gate_kernel<<<BS, 256, 0, s0>>>(summary, m_seq, gate_w, gate_b, wgtp, cntp, listp);
    gemmS(s0, qbf, 3072, 6144, 768, wbf + W_EXPW1, 768LL*768, 768, exp_b1, IN_, nullptr,
          nullptr, 0, h1bf, (long long)BS * 1536, nullptr, nullptr, nullptr,
          listp, cntp, 1, 768, NS_, 1);
    gemmS(s0, h1bf, 768, 1536, (long long)BS * 1536, wbf + W_EXPW2, 512LL*768, 768,
          exp_b2, D_, nullptr, experts, BSD, nullptr, 0,
          nullptr, nullptr, nullptr, listp, cntp, 2, 512, NS_, 0);
    moe_kernel<<<BS, 256, 0, s0>>>(wgtp, experts, moe_g, moe_b, pe, x, xbf);

    // --- join: layer loop needs vth (s2) and xbf (s0) ---
    cudaStreamWaitEvent(s0, evJoin, 0);

    for (int i = 0; i < L_; i++) {
        gemmS(s0, xbf, 512, 1024, 0, wbf + W_KW + (long long)i * 262144, 0, 512,
              kb + i*D_, 0, nullptr, nullptr, 0, nullptr, 0,
              khh, khl, nullptr, nullptr, nullptr, 0, 512, 1, 0);
        attn_mma_kernel<<<dim3(16, 32), 128, ATTN_SMEM, s0>>>(
            khh, khl, vth + (long long)i * 2097152, ctxbf);
        gemmS(s0, ctxbf, 512, 1024, 0, wbf + W_OW + (long long)i * 262144, 0, 512,
              ob + i*D_, 0, x, x, 0, nullptr, 0,
              nullptr, nullptr, nullptr, nullptr, nullptr, 0, 512, 1, 0);
        ln_kernel<<<BS, 256, 0, s0>>>(x, ln1g + i*D_, ln1b + i*D_, x, xbf);
        gemmS(s0, xbf, 512, 1024, 0, wbf + W_FW1 + (long long)i * 1048576, 0, 512,
              fb1 + i*FF_, 0, nullptr, nullptr, 0, ffnbf, 0,
              nullptr, nullptr, nullptr, nullptr, nullptr, 0, 2048, 1, 1);
        gemmS(s0, ffnbf, 2048, 4096, 0, wbf + W_FW2 + (long long)i * 1048576, 0, 2048,
              fb2 + i*D_, 0, x, x, 0, nullptr, 0,
              nullptr, nullptr, nullptr, nullptr, nullptr, 0, 512, 1, 0);
        ln_kernel<<<BS, 256, 0, s0>>>(x, ln2g + i*D_, ln2b + i*D_,
                               (i == L_-1) ? (float*)d_out : x,
                               (i == L_-1) ? nullptr : xbf);
    }
}

// round 16
// speedup vs baseline: 1.0300x; 1.0300x over previous
#include <cuda_runtime.h>
#include <cuda_fp16.h>
#include <cstdint>
#include <math.h>

// Problem dims
#define B_  4
#define S_  1024
#define D_  512
#define H_  8
#define DK_ 64
#define FF_ 2048
#define L_  4
#define IN_ 768
#define NS_ 4
#define SD_ 64

#define BS  (B_*S_)            // 4096
#define BSD ((long long)BS*D_) // 2097152
#define NEG_INF __int_as_float(0xff800000)

// ---------------- scratch (device globals: allocation-free) ----------------
__device__ float g_pe[S_*D_];
__device__ float g_x[BS*D_];
__device__ float g_experts[NS_*BS*D_];
__device__ float g_summary[BS*D_];
__device__ float g_wgt[BS*4];
__device__ int   g_cnt[4];
__device__ int   g_list[4*BS];
// split fp16 buffers, layout [m][hi K | lo K]
__device__ __half g_qbf[25165824];    // q_raw' [4096][6144]
__device__ __half g_h1bf[25165824];   // h1'   [4][4096][1536] (compacted slots)
__device__ __half g_ybf[4194304];     // y'    [4096][1024]
__device__ __half g_xbf[4194304];     // x'    [4096][1024]
__device__ __half g_ctxbf[4194304];   // ctx'  [4096][1024]
__device__ __half g_ffnbf[16777216];  // ffn'  [4096][4096]
__device__ __half g_khh[2097152];     // K hi [32][1024][64]
__device__ __half g_khl[2097152];     // K lo
__device__ __half g_vth[8388608];     // Vt hi [4][32][64][1024]
// all weights, SINGLE fp16 [n][K]
__device__ __half g_wbf[17039360];

// weight buffer offsets (fp16 elements)
#define W_EXPW1 0LL
#define W_EXPW2 2359296LL
#define W_ADAPT 3932160LL
#define W_KW    5505024LL
#define W_VW    6553600LL
#define W_OW    7602176LL
#define W_FW1   8650752LL
#define W_FW2   12845056LL

// ================= PTX helpers ===============================================
__device__ __forceinline__ uint32_t smem_u32(const void* p) {
    uint32_t a;
    asm("{ .reg .u64 t; cvta.to.shared.u64 t, %1; cvt.u32.u64 %0, t; }" : "=r"(a) : "l"(p));
    return a;
}
__device__ __forceinline__ void cp_async16(uint32_t dst, const void* src) {
    asm volatile("cp.async.cg.shared.global [%0], [%1], 16;" :: "r"(dst), "l"(src));
}
#define CP_COMMIT() asm volatile("cp.async.commit_group;" ::: "memory")
#define CP_WAIT0()  asm volatile("cp.async.wait_group 0;" ::: "memory")
#define CP_WAIT1()  asm volatile("cp.async.wait_group 1;" ::: "memory")

__device__ __forceinline__ void ldsm_x4(uint32_t& r0, uint32_t& r1, uint32_t& r2,
                                        uint32_t& r3, uint32_t addr) {
    asm volatile("ldmatrix.sync.aligned.m8n8.x4.shared.b16 {%0,%1,%2,%3}, [%4];"
        : "=r"(r0), "=r"(r1), "=r"(r2), "=r"(r3) : "r"(addr));
}
__device__ __forceinline__ void mma16816(float* c, const uint32_t* a, const uint32_t* b) {
    asm volatile(
        "mma.sync.aligned.m16n8k16.row.col.f32.f16.f16.f32 "
        "{%0,%1,%2,%3}, {%4,%5,%6,%7}, {%8,%9}, {%0,%1,%2,%3};"
        : "+f"(c[0]), "+f"(c[1]), "+f"(c[2]), "+f"(c[3])
        : "r"(a[0]), "r"(a[1]), "r"(a[2]), "r"(a[3]), "r"(b[0]), "r"(b[1]));
}
__device__ __forceinline__ uint32_t pack_h2(float lo, float hi) {
    uint32_t d;
    asm("cvt.rn.f16x2.f32 %0, %1, %2;" : "=r"(d) : "f"(hi), "f"(lo));
    return d;
}
__device__ __forceinline__ float h2_lo(uint32_t p) {
    return __half2float(__ushort_as_half((unsigned short)(p & 0xffff)));
}
__device__ __forceinline__ float h2_hi(uint32_t p) {
    return __half2float(__ushort_as_half((unsigned short)(p >> 16)));
}

__device__ __forceinline__ uint32_t swz(uint32_t base, int r, int ch) {
    return base + r * 128 + ((ch ^ (r & 7)) << 4);
}

// ================= conversions ==============================================
// q_raw [4096][3072] fp32 -> q' [4096][6144] = [hi 3072 | lo 3072]
__global__ __launch_bounds__(256) void conv_qraw_kernel(
    const float* __restrict__ src, __half* __restrict__ dst)
{
    int idx = blockIdx.x * 256 + threadIdx.x;
    int m = idx / 768;
    int k = (idx - m * 768) * 4;
    float4 v = *(const float4*)(src + (long long)m * 3072 + k);
    unsigned short hb[4], lb[4];
    float vv[4] = {v.x, v.y, v.z, v.w};
    #pragma unroll
    for (int i = 0; i < 4; i++) {
        __half h = __float2half_rn(vv[i]);
        __half l = __float2half_rn(vv[i] - __half2float(h));
        hb[i] = __half_as_ushort(h);
        lb[i] = __half_as_ushort(l);
    }
    long long base = (long long)m * 6144;
    *(uint2*)(dst + base + k) = make_uint2((uint32_t)hb[0] | ((uint32_t)hb[1] << 16),
                                           (uint32_t)hb[2] | ((uint32_t)hb[3] << 16));
    *(uint2*)(dst + base + 3072 + k) = make_uint2((uint32_t)lb[0] | ((uint32_t)lb[1] << 16),
                                                  (uint32_t)lb[2] | ((uint32_t)lb[3] << 16));
}

// all weights W [z][K][N] fp32 -> W' [z][n][K] single fp16, one launch
struct ConvSegs {
    const float* src[8];
    long long dstOff[8];
    int K[8], N[8], tOff[8];
};

__global__ void convB_all_kernel(ConvSegs segs, __half* __restrict__ wb)
{
    __shared__ float t[32][33];
    int bx = blockIdx.x;
    int seg = 0;
    #pragma unroll
    for (int i = 7; i >= 1; i--) if (bx >= segs.tOff[i]) { seg = i; break; }
    const int K = segs.K[seg], N = segs.N[seg];
    int tl = bx - segs.tOff[seg];
    int tz = (K >> 5) * (N >> 5);
    int z = tl / tz, rr = tl - z * tz;
    int k0 = (rr % (K >> 5)) * 32, n0 = (rr / (K >> 5)) * 32;
    const float* s = segs.src[seg] + (long long)z * K * N;
    __half* dstz = wb + segs.dstOff[seg] + (long long)z * N * K;
    int tx = threadIdx.x, ty = threadIdx.y;
    #pragma unroll
    for (int r = ty; r < 32; r += 8)
        t[r][tx] = s[(long long)(k0 + r) * N + n0 + tx];
    __syncthreads();
    #pragma unroll
    for (int r = ty; r < 32; r += 8) {
        dstz[(long long)(n0 + r) * K + k0 + tx] = __float2half_rn(t[tx][r]);
    }
}

// ================= unified split GEMM (fp16, 2 terms: Xh*W + Xl*W) ==========
// 256 threads, 8 warps, warp tile 32x32 over 128x64 CTA tile, 2-stage, 2 CTA/SM.
// gmode: 0 = dense, 1 = gather-A rows via list (Sp at slots), 2 = scatter-C rows
#define G2_STAGE 40960
#define G2_SMEM  81920

__global__ __launch_bounds__(256, 2) void gemm2_kernel(
    const __half* __restrict__ Ah0, int loA, int ldA, long long zA,
    const __half* __restrict__ Bt0, long long zB, int K,
    const float* __restrict__ bias, int sBias,
    const float* __restrict__ res,
    float* __restrict__ C, long long sC,
    __half* __restrict__ Sp, long long zSp,
    __half* __restrict__ KH, __half* __restrict__ KL,
    __half* __restrict__ VH,
    const int* __restrict__ glist, const int* __restrict__ gcnt,
    int gmode, int N, int relu)
{
    extern __shared__ __align__(1024) char smem[];
    __shared__ int slist[128];
    const int tid = threadIdx.x, wid = tid >> 5, lane = tid & 31;
    const int wy = wid >> 1, wx = wid & 1;       // 4x2 warps, 32x32 each
    const int z = blockIdx.z;
    const int brow = blockIdx.y * 128, bcol = blockIdx.x * 64;

    int cnt = 0;
    if (gmode) {
        cnt = gcnt[z];
        if (brow >= cnt) return;
        if (tid < 128) {
            int i = brow + tid;
            slist[tid] = glist[z * BS + (i < cnt ? i : cnt - 1)];
        }
    }

    const __half* Ahz = Ah0 + (long long)z * zA;
    const __half* Bh = Bt0 + (long long)z * zB + (long long)bcol * K;
    if (bias) bias += (long long)z * sBias;
    if (C) C += (long long)z * sC;
    if (Sp) Sp += (long long)z * zSp;

    if (gmode) __syncthreads();

    const uint32_t sb = smem_u32(smem);
    const int NC = K >> 6;

    // stage layout: Ah 16K @0, Al 16K @16384, B 8K @32768 (40K total)
    auto load_tile = [&](int c, int s) {
        const int kc = c * 64;
        const uint32_t st = sb + s * G2_STAGE;
        #pragma unroll
        for (int i = 0; i < 10; i++) {
            int idx = tid + i * 256;          // 0..2559
            if (idx < 1024) {
                int r = idx >> 3, ch = idx & 7;
                int rowA = (gmode == 1) ? slist[r] : (brow + r);
                cp_async16(swz(st, r, ch),
                           (const char*)(Ahz + (long long)rowA * ldA + kc) + ch * 16);
            } else if (idx < 2048) {
                int j = idx - 1024;
                int r = j >> 3, ch = j & 7;
                int rowA = (gmode == 1) ? slist[r] : (brow + r);
                cp_async16(swz(st + 16384, r, ch),
                           (const char*)(Ahz + loA + (long long)rowA * ldA + kc) + ch * 16);
            } else {
                int j = idx - 2048;
                int r = j >> 3, ch = j & 7;
                cp_async16(swz(st + 32768, r, ch),
                           (const char*)(Bh + (long long)r * K + kc) + ch * 16);
            }
        }
        CP_COMMIT();
    };

    float acc[2][4][4] = {};
    load_tile(0, 0);
    load_tile(1, 1);

    for (int c = 0; c < NC; c++) {
        const int s = c & 1;
        if (c + 1 < NC) { CP_WAIT1(); } else { CP_WAIT0(); }
        __syncthreads();
        const uint32_t stA = sb + s * G2_STAGE;

        #pragma unroll
        for (int ks = 0; ks < 4; ks++) {
            const int cb = ks * 2;
            uint32_t ah[2][4], al[2][4];
            #pragma unroll
            for (int ms = 0; ms < 2; ms++) {
                int r = wy * 32 + ms * 16 + (lane & 15);
                int ch = cb + (lane >> 4);
                ldsm_x4(ah[ms][0], ah[ms][1], ah[ms][2], ah[ms][3], swz(stA, r, ch));
                ldsm_x4(al[ms][0], al[ms][1], al[ms][2], al[ms][3], swz(stA + 16384, r, ch));
            }
            uint32_t bh[4][2];
            #pragma unroll
            for (int nh = 0; nh < 2; nh++) {
                int g = lane >> 3;
                int r = wx * 32 + nh * 16 + ((g & 2) << 2) + (lane & 7);
                int ch = cb + (g & 1);
                uint32_t r0, r1, r2, r3;
                ldsm_x4(r0, r1, r2, r3, swz(stA + 32768, r, ch));
                bh[nh*2][0] = r0; bh[nh*2][1] = r1;
                bh[nh*2+1][0] = r2; bh[nh*2+1][1] = r3;
            }
            // term-major: 8 independent accumulators between reuses
            #pragma unroll
            for (int ms = 0; ms < 2; ms++)
                #pragma unroll
                for (int ns = 0; ns < 4; ns++)
                    mma16816(acc[ms][ns], ah[ms], bh[ns]);
            #pragma unroll
            for (int ms = 0; ms < 2; ms++)
                #pragma unroll
                for (int ns = 0; ns < 4; ns++)
                    mma16816(acc[ms][ns], al[ms], bh[ns]);
        }
        __syncthreads();
        if (c + 2 < NC) load_tile(c + 2, s);
    }

    // ---- epilogue ----
    const int qrow = lane >> 2, qcol = (lane & 3) * 2;
    #pragma unroll
    for (int ms = 0; ms < 2; ms++) {
        int m = brow + wy * 32 + ms * 16 + qrow;
        bool ok0 = !gmode || (m < cnt);
        bool ok1 = !gmode || (m + 8 < cnt);
        int crow0 = (gmode == 2 && ok0) ? slist[m - brow] : m;
        int crow1 = (gmode == 2 && ok1) ? slist[m + 8 - brow] : m + 8;
        #pragma unroll
        for (int ns = 0; ns < 4; ns++) {
            int n = bcol + wx * 32 + ns * 8 + qcol;
            float2 v0 = make_float2(acc[ms][ns][0], acc[ms][ns][1]);
            float2 v1 = make_float2(acc[ms][ns][2], acc[ms][ns][3]);
            if (bias) {
                float b0 = bias[n], b1 = bias[n + 1];
                v0.x += b0; v0.y += b1; v1.x += b0; v1.y += b1;
            }
            if (res) {
                float2 r0 = *(const float2*)(res + (long long)m * N + n);
                float2 r1 = *(const float2*)(res + (long long)(m + 8) * N + n);
                v0.x += r0.x; v0.y += r0.y; v1.x += r1.x; v1.y += r1.y;
            }
            if (relu) {
                v0.x = fmaxf(v0.x, 0.f); v0.y = fmaxf(v0.y, 0.f);
                v1.x = fmaxf(v1.x, 0.f); v1.y = fmaxf(v1.y, 0.f);
            }
            if (C) {
                if (ok0) *(float2*)(C + (long long)crow0 * N + n) = v0;
                if (ok1) *(float2*)(C + (long long)crow1 * N + n) = v1;
            }
            uint32_t hp0 = pack_h2(v0.x, v0.y);
            uint32_t hp1 = pack_h2(v1.x, v1.y);
            uint32_t lp0 = pack_h2(v0.x - h2_lo(hp0), v0.y - h2_hi(hp0));
            uint32_t lp1 = pack_h2(v1.x - h2_lo(hp1), v1.y - h2_hi(hp1));
            if (Sp) {
                long long r0 = (long long)m * 2 * N, r1 = (long long)(m + 8) * 2 * N;
                if (ok0) {
                    *(uint32_t*)(Sp + r0 + n)     = hp0;
                    *(uint32_t*)(Sp + r0 + N + n) = lp0;
                }
                if (ok1) {
                    *(uint32_t*)(Sp + r1 + n)     = hp1;
                    *(uint32_t*)(Sp + r1 + N + n) = lp1;
                }
            }
            if (KH) {
                long long a0 = (((long long)((m >> 10) * 8 + (n >> 6))) * 1024 + (m & 1023)) * 64 + (n & 63);
                long long a1 = a0 + 8LL * 64;
                *(uint32_t*)(KH + a0) = hp0;  *(uint32_t*)(KL + a0) = lp0;
                *(uint32_t*)(KH + a1) = hp1;  *(uint32_t*)(KL + a1) = lp1;
            }
            if (VH) {
                int b = m >> 10, h = n >> 6, d = n & 63, si = m & 1023;
                long long base = (((long long)(z * 32 + b * 8 + h)) * 64 + d) * 1024 + si;
                unsigned short* vh = (unsigned short*)VH;
                vh[base]            = (unsigned short)(hp0 & 0xffff);
                vh[base + 1024]     = (unsigned short)(hp0 >> 16);
                vh[base + 8]        = (unsigned short)(hp1 & 0xffff);
                vh[base + 1024 + 8] = (unsigned short)(hp1 >> 16);
            }
        }
    }
}

// ================= tensor-core flash attention (fp16 2-term) =================
// smem: Qhi @0 (8K), Qlo @8192; stages @16384 + s*16384: {Khi 8K, Vhi 8K}
#define ATTN_SMEM 49152

__global__ __launch_bounds__(128) void attn_mma_kernel(
    const __half* __restrict__ khh, const __half* __restrict__ khl,
    const __half* __restrict__ vth,
    __half* __restrict__ Cx)
{
    extern __shared__ __align__(1024) char smem[];
    const uint32_t sb = smem_u32(smem);
    const int tid = threadIdx.x, wid = tid >> 5, lane = tid & 31;
    const int qb = 15 - blockIdx.x;
    const int bh = blockIdx.y;
    const int q0 = qb * 64;

    const __half* Kh = khh + (long long)bh * S_ * 64;
    const __half* Kl = khl + (long long)bh * S_ * 64;
    const __half* Vh = vth + (long long)bh * 64 * S_;

    auto load_kv = [&](int jt, int s) {
        const int j0 = jt * 64;
        const uint32_t base = sb + 16384 + s * 16384;
        #pragma unroll
        for (int i = 0; i < 4; i++) {
            int idx = tid + i * 128;
            int r = idx >> 3, ch = idx & 7;
            cp_async16(swz(base, r, ch),
                       (const char*)(Kh + (long long)(j0 + r) * 64) + ch * 16);
            cp_async16(swz(base + 8192, r, ch),
                       (const char*)(Vh + (long long)r * S_ + j0) + ch * 16);
        }
        CP_COMMIT();
    };

    #pragma unroll
    for (int i = 0; i < 4; i++) {
        int idx = tid + i * 128;
        int r = idx >> 3, ch = idx & 7;
        cp_async16(swz(sb, r, ch),
                   (const char*)(Kh + (long long)(q0 + r) * 64) + ch * 16);
        cp_async16(swz(sb + 8192, r, ch),
                   (const char*)(Kl + (long long)(q0 + r) * 64) + ch * 16);
    }
    load_kv(0, 0);
    CP_WAIT0();
    __syncthreads();

    uint32_t qh[4][4], ql[4][4];
    #pragma unroll
    for (int ks = 0; ks < 4; ks++) {
        int r = wid * 16 + (lane & 15);
        int ch = 2 * ks + (lane >> 4);
        ldsm_x4(qh[ks][0], qh[ks][1], qh[ks][2], qh[ks][3], swz(sb, r, ch));
        ldsm_x4(ql[ks][0], ql[ks][1], ql[ks][2], ql[ks][3], swz(sb + 8192, r, ch));
    }

    float ctx[8][4] = {};
    float m0 = NEG_INF, m1 = NEG_INF, l0 = 0.f, l1 = 0.f;
    const int rg0 = q0 + wid * 16 + (lane >> 2);

    for (int jt = 0; jt <= qb; jt++) {
        const int s = jt & 1;
        if (jt < qb) { load_kv(jt + 1, s ^ 1); CP_WAIT1(); }
        else if (jt > 0) { CP_WAIT0(); }
        __syncthreads();

        const uint32_t bK = sb + 16384 + s * 16384;

        float sc[8][4] = {};
        #pragma unroll
        for (int ks = 0; ks < 4; ks++) {
            uint32_t bh_[8][2];
            #pragma unroll
            for (int ng = 0; ng < 4; ng++) {
                int g = lane >> 3;
                int r = ng * 16 + ((g & 2) << 2) + (lane & 7);
                int ch = 2 * ks + (g & 1);
                uint32_t a0, a1, a2, a3;
                ldsm_x4(a0, a1, a2, a3, swz(bK, r, ch));
                bh_[2*ng][0] = a0; bh_[2*ng][1] = a1;
                bh_[2*ng+1][0] = a2; bh_[2*ng+1][1] = a3;
            }
            #pragma unroll
            for (int nt = 0; nt < 8; nt++) {
                mma16816(sc[nt], qh[ks], bh_[nt]);
                mma16816(sc[nt], ql[ks], bh_[nt]);
            }
        }

        const int j0 = jt * 64;
        const bool diag = (jt == qb);
        const int cb0 = j0 + (lane & 3) * 2;
        float rm0 = NEG_INF, rm1 = NEG_INF;
        #pragma unroll
        for (int nt = 0; nt < 8; nt++) {
            int c0 = cb0 + nt * 8, c1 = c0 + 1;
            float s0 = sc[nt][0] * 0.125f, s1 = sc[nt][1] * 0.125f;
            float s2 = sc[nt][2] * 0.125f, s3 = sc[nt][3] * 0.125f;
            if (diag) {
                if (c0 >= rg0)     s0 = NEG_INF;
                if (c1 >= rg0)     s1 = NEG_INF;
                if (c0 >= rg0 + 8) s2 = NEG_INF;
                if (c1 >= rg0 + 8) s3 = NEG_INF;
            }
            sc[nt][0] = s0; sc[nt][1] = s1; sc[nt][2] = s2; sc[nt][3] = s3;
            rm0 = fmaxf(rm0, fmaxf(s0, s1));
            rm1 = fmaxf(rm1, fmaxf(s2, s3));
        }
        #pragma unroll
        for (int o = 1; o <= 2; o <<= 1) {
            rm0 = fmaxf(rm0, __shfl_xor_sync(0xffffffffu, rm0, o));
            rm1 = fmaxf(rm1, __shfl_xor_sync(0xffffffffu, rm1, o));
        }
        float mn0 = fmaxf(m0, rm0), mn1 = fmaxf(m1, rm1);
        float ms0 = (mn0 == NEG_INF) ? 0.f : mn0;
        float ms1 = (mn1 == NEG_INF) ? 0.f : mn1;
        float cr0 = __expf(m0 - ms0), cr1 = __expf(m1 - ms1);
        float rs0 = 0.f, rs1 = 0.f;
        #pragma unroll
        for (int nt = 0; nt < 8; nt++) {
            sc[nt][0] = __expf(sc[nt][0] - ms0); rs0 += sc[nt][0];
            sc[nt][1] = __expf(sc[nt][1] - ms0); rs0 += sc[nt][1];
            sc[nt][2] = __expf(sc[nt][2] - ms1); rs1 += sc[nt][2];
            sc[nt][3] = __expf(sc[nt][3] - ms1); rs1 += sc[nt][3];
        }
        #pragma unroll
        for (int o = 1; o <= 2; o <<= 1) {
            rs0 += __shfl_xor_sync(0xffffffffu, rs0, o);
            rs1 += __shfl_xor_sync(0xffffffffu, rs1, o);
        }
        l0 = l0 * cr0 + rs0; l1 = l1 * cr1 + rs1;
        m0 = mn0; m1 = mn1;
        #pragma unroll
        for (int nt = 0; nt < 8; nt++) {
            ctx[nt][0] *= cr0; ctx[nt][1] *= cr0;
            ctx[nt][2] *= cr1; ctx[nt][3] *= cr1;
        }

        uint32_t ph[4][4], pl[4][4];
        #pragma unroll
        for (int kj = 0; kj < 4; kj++) {
            const int t0 = 2 * kj, t1 = 2 * kj + 1;
            ph[kj][0] = pack_h2(sc[t0][0], sc[t0][1]);
            ph[kj][1] = pack_h2(sc[t0][2], sc[t0][3]);
            ph[kj][2] = pack_h2(sc[t1][0], sc[t1][1]);
            ph[kj][3] = pack_h2(sc[t1][2], sc[t1][3]);
            pl[kj][0] = pack_h2(sc[t0][0] - h2_lo(ph[kj][0]), sc[t0][1] - h2_hi(ph[kj][0]));
            pl[kj][1] = pack_h2(sc[t0][2] - h2_lo(ph[kj][1]), sc[t0][3] - h2_hi(ph[kj][1]));
            pl[kj][2] = pack_h2(sc[t1][0] - h2_lo(ph[kj][2]), sc[t1][1] - h2_hi(ph[kj][2]));
            pl[kj][3] = pack_h2(sc[t1][2] - h2_lo(ph[kj][3]), sc[t1][3] - h2_hi(ph[kj][3]));
        }

        const uint32_t bV = bK + 8192;
        #pragma unroll
        for (int kj = 0; kj < 4; kj++) {
            uint32_t vh_[8][2];
            #pragma unroll
            for (int dg = 0; dg < 4; dg++) {
                int g = lane >> 3;
                int r = dg * 16 + ((g & 2) << 2) + (lane & 7);
                int ch = 2 * kj + (g & 1);
                uint32_t a0, a1, a2, a3;
                ldsm_x4(a0, a1, a2, a3, swz(bV, r, ch));
                vh_[2*dg][0] = a0; vh_[2*dg][1] = a1;
                vh_[2*dg+1][0] = a2; vh_[2*dg+1][1] = a3;
            }
            #pragma unroll
            for (int nt = 0; nt < 8; nt++) {
                mma16816(ctx[nt], ph[kj], vh_[nt]);
                mma16816(ctx[nt], pl[kj], vh_[nt]);
            }
        }
        __syncthreads();
    }

    float inv0 = (l0 > 0.f) ? 1.f / l0 : 0.f;
    float inv1 = (l1 > 0.f) ? 1.f / l1 : 0.f;
    const int b = bh >> 3, h = bh & 7;
    const int row0 = b * S_ + q0 + wid * 16 + (lane >> 2);
    const int colb = h * 64 + (lane & 3) * 2;
    #pragma unroll
    for (int nt = 0; nt < 8; nt++) {
        float a0 = ctx[nt][0] * inv0, a1 = ctx[nt][1] * inv0;
        float a2 = ctx[nt][2] * inv1, a3 = ctx[nt][3] * inv1;
        uint32_t hp0 = pack_h2(a0, a1);
        uint32_t hp1 = pack_h2(a2, a3);
        uint32_t lp0 = pack_h2(a0 - h2_lo(hp0), a1 - h2_hi(hp0));
        uint32_t lp1 = pack_h2(a2 - h2_lo(hp1), a3 - h2_hi(hp1));
        long long r0 = (long long)row0 * 1024, r1 = (long long)(row0 + 8) * 1024;
        int cc = colb + nt * 8;
        *(uint32_t*)(Cx + r0 + cc)       = hp0;
        *(uint32_t*)(Cx + r0 + 512 + cc) = lp0;
        *(uint32_t*)(Cx + r1 + cc)       = hp1;
        *(uint32_t*)(Cx + r1 + 512 + cc) = lp1;
    }
}

// ---------------- positional embedding (also zero gate counters) -----------
__global__ void pe_kernel(float* __restrict__ pe) {
    if (blockIdx.x == 0 && threadIdx.x < 4) g_cnt[threadIdx.x] = 0;
    int s = blockIdx.x;
    int j = threadIdx.x;
    float div = expf((float)(2*j) * (-9.210340371976184f / (float)D_));
    float arg = (float)s * div;
    pe[s*D_ + 2*j]     = sinf(arg);
    pe[s*D_ + 2*j + 1] = cosf(arg);
}

__global__ __launch_bounds__(256) void add_pe_kernel(
    const float* __restrict__ qa, const float* __restrict__ pe,
    __half* __restrict__ yb)
{
    int i = blockIdx.x * 256 + threadIdx.x;
    float v = qa[i] + pe[i & (S_*D_ - 1)];
    int m = i >> 9, c = i & 511;
    __half h = __float2half_rn(v);
    yb[(long long)m * 1024 + c]       = h;
    yb[(long long)m * 1024 + 512 + c] = __float2half_rn(v - __half2float(h));
}

// ---------------- gate: logits -> top-2 weights + expert row lists ----------
__global__ __launch_bounds__(256) void gate_kernel(
    const float* __restrict__ summary, const float* __restrict__ m_seq,
    const float* __restrict__ gate_w,  const float* __restrict__ gate_b,
    float* __restrict__ wgt, int* __restrict__ cnt, int* __restrict__ list)
{
    __shared__ float red[4][8];
    const int row = blockIdx.x;
    const int tid = threadIdx.x;

    float p0 = 0, p1 = 0, p2 = 0, p3 = 0;
    for (int e = tid; e < D_ + SD_; e += 256) {
        float xv = (e < D_) ? summary[(long long)row * D_ + e]
                            : m_seq[(long long)row * SD_ + (e - D_)];
        float4 w = *(const float4*)(gate_w + e * 4);
        p0 += xv * w.x; p1 += xv * w.y; p2 += xv * w.z; p3 += xv * w.w;
    }
    #pragma unroll
    for (int o = 16; o > 0; o >>= 1) {
        p0 += __shfl_xor_sync(0xffffffffu, p0, o);
        p1 += __shfl_xor_sync(0xffffffffu, p1, o);
        p2 += __shfl_xor_sync(0xffffffffu, p2, o);
        p3 += __shfl_xor_sync(0xffffffffu, p3, o);
    }
    if ((tid & 31) == 0) {
        int w = tid >> 5;
        red[0][w] = p0; red[1][w] = p1; red[2][w] = p2; red[3][w] = p3;
    }
    __syncthreads();

    if (tid == 0) {
        float l[4];
        #pragma unroll
        for (int j = 0; j < 4; j++) {
            float t = gate_b[j];
            #pragma unroll
            for (int w = 0; w < 8; w++) t += red[j][w];
            l[j] = t;
        }
        float m1v = -INFINITY, m2v = -INFINITY;
        #pragma unroll
        for (int j = 0; j < 4; j++) {
            if (l[j] > m1v) { m2v = m1v; m1v = l[j]; }
            else if (l[j] > m2v) { m2v = l[j]; }
        }
        float sum = 0.f, e4[4];
        #pragma unroll
        for (int j = 0; j < 4; j++) {
            e4[j] = (l[j] >= m2v) ? __expf(l[j] - m1v) : 0.f;
            sum += e4[j];
        }
        #pragma unroll
        for (int j = 0; j < 4; j++) {
            wgt[row * 4 + j] = e4[j] / sum;
            if (l[j] >= m2v) {
                int p = atomicAdd(&cnt[j], 1);
                list[j * BS + p] = row;
            }
        }
    }
}

// ---------------- MoE combine + LN + PE -> x (fp32 + split) ----------------
__global__ __launch_bounds__(256) void moe_kernel(
    const float* __restrict__ wgt, const float* __restrict__ experts,
    const float* __restrict__ lng, const float* __restrict__ lnb,
    const float* __restrict__ pe, float* __restrict__ x,
    __half* __restrict__ xb)
{
    __shared__ float r1[8], r2[8];
    const int row = blockIdx.x;
    const int tid = threadIdx.x;
    const int s_idx = row & (S_ - 1);

    const float w0 = wgt[row*4], w1 = wgt[row*4+1], w2 = wgt[row*4+2], w3 = wgt[row*4+3];
    const long long base = (long long)row * D_;
    const int t2 = tid + 256;
    float c0 = w0 * experts[0*BSD + base + tid] + w1 * experts[1*BSD + base + tid]
             + w2 * experts[2*BSD + base + tid] + w3 * experts[3*BSD + base + tid];
    float c1 = w0 * experts[0*BSD + base + t2]  + w1 * experts[1*BSD + base + t2]
             + w2 * experts[2*BSD + base + t2]  + w3 * experts[3*BSD + base + t2];

    float s = c0 + c1, q = c0 * c0 + c1 * c1;
    #pragma unroll
    for (int o = 16; o > 0; o >>= 1) {
        s += __shfl_xor_sync(0xffffffffu, s, o);
        q += __shfl_xor_sync(0xffffffffu, q, o);
    }
    if ((tid & 31) == 0) { r1[tid >> 5] = s; r2[tid >> 5] = q; }
    __syncthreads();
    float ts = 0, tq = 0;
    #pragma unroll
    for (int w = 0; w < 8; w++) { ts += r1[w]; tq += r2[w]; }
    float mu = ts * (1.f / 512.f);
    float var = tq * (1.f / 512.f) - mu * mu;
    float rstd = rsqrtf(var + 1e-5f);

    float o0 = (c0 - mu) * rstd * lng[tid] + lnb[tid] + pe[s_idx * D_ + tid];
    float o1 = (c1 - mu) * rstd * lng[t2]  + lnb[t2]  + pe[s_idx * D_ + t2];
    x[base + tid] = o0;
    x[base + t2]  = o1;
    long long b2 = (long long)row * 1024;
    __half h0 = __float2half_rn(o0);
    __half h1 = __float2half_rn(o1);
    xb[b2 + tid]        = h0;
    xb[b2 + t2]         = h1;
    xb[b2 + 512 + tid]  = __float2half_rn(o0 - __half2float(h0));
    xb[b2 + 512 + t2]   = __float2half_rn(o1 - __half2float(h1));
}

// ---------------- LayerNorm (fp32 out + optional split) --------------------
__global__ __launch_bounds__(256) void ln_kernel(
    const float* __restrict__ in, const float* __restrict__ g,
    const float* __restrict__ b, float* __restrict__ out,
    __half* __restrict__ sp)
{
    __shared__ float r1[8], r2[8];
    const int row = blockIdx.x, tid = threadIdx.x;
    const long long base = (long long)row * D_;
    float v0 = in[base + tid], v1 = in[base + tid + 256];
    float s = v0 + v1, q = v0 * v0 + v1 * v1;
    #pragma unroll
    for (int o = 16; o > 0; o >>= 1) {
        s += __shfl_xor_sync(0xffffffffu, s, o);
        q += __shfl_xor_sync(0xffffffffu, q, o);
    }
    if ((tid & 31) == 0) { r1[tid >> 5] = s; r2[tid >> 5] = q; }
    __syncthreads();
    float ts = 0, tq = 0;
    #pragma unroll
    for (int w = 0; w < 8; w++) { ts += r1[w]; tq += r2[w]; }
    float mu = ts * (1.f / 512.f);
    float var = tq * (1.f / 512.f) - mu * mu;
    float rstd = rsqrtf(var + 1e-5f);
    float o0 = (v0 - mu) * rstd * g[tid]       + b[tid];
    float o1 = (v1 - mu) * rstd * g[tid + 256] + b[tid + 256];
    out[base + tid]       = o0;
    out[base + tid + 256] = o1;
    if (sp) {
        long long b2 = (long long)row * 1024;
        __half h0 = __float2half_rn(o0);
        __half h1 = __float2half_rn(o1);
        sp[b2 + tid]       = h0;
        sp[b2 + tid + 256] = h1;
        sp[b2 + 512 + tid]       = __float2half_rn(o0 - __half2float(h0));
        sp[b2 + 512 + tid + 256] = __float2half_rn(o1 - __half2float(h1));
    }
}

// ================= host wrapper ==============================================
typedef __half h16;

static void gemmS(cudaStream_t st,
                  const h16* Ah, int loA, int ldA, long long zA,
                  const h16* Bt, long long zB, int K,
                  const float* bias, int sBias, const float* res,
                  float* C, long long sC, h16* Sp, long long zSp,
                  h16* KH, h16* KL, h16* VH,
                  const int* glist, const int* gcnt, int gmode,
                  int N, int nz, int relu)
{
    gemm2_kernel<<<dim3(N/64, 32, nz), 256, G2_SMEM, st>>>(
        Ah, loA, ldA, zA, Bt, zB, K, bias, sBias, res, C, sC,
        Sp, zSp, KH, KL, VH, glist, gcnt, gmode, N, relu);
}

extern "C" void kernel_launch(void* const* d_in, const int* in_sizes, int n_in,
                              void* d_out, int out_size)
{
    const float* q_raw   = (const float*)d_in[0];
    const float* m_seq   = (const float*)d_in[1];
    const float* qa      = (const float*)d_in[2];
    const float* exp_w1  = (const float*)d_in[3];
    const float* exp_b1  = (const float*)d_in[4];
    const float* exp_w2  = (const float*)d_in[5];
    const float* exp_b2  = (const float*)d_in[6];
    const float* adapt_w = (const float*)d_in[7];
    const float* adapt_b = (const float*)d_in[8];
    const float* gate_w  = (const float*)d_in[9];
    const float* gate_b  = (const float*)d_in[10];
    const float* moe_g   = (const float*)d_in[11];
    const float* moe_b   = (const float*)d_in[12];
    const float* kw      = (const float*)d_in[13];
    const float* kb      = (const float*)d_in[14];
    const float* vw      = (const float*)d_in[15];
    const float* vb      = (const float*)d_in[16];
    const float* ow      = (const float*)d_in[17];
    const float* ob      = (const float*)d_in[18];
    const float* ln1g    = (const float*)d_in[19];
    const float* ln1b    = (const float*)d_in[20];
    const float* fw1     = (const float*)d_in[21];
    const float* fb1     = (const float*)d_in[22];
    const float* fw2     = (const float*)d_in[23];
    const float* fb2     = (const float*)d_in[24];
    const float* ln2g    = (const float*)d_in[25];
    const float* ln2b    = (const float*)d_in[26];

    float *pe, *x, *experts, *summary, *wgtp;
    int *cntp, *listp;
    h16 *qbf, *h1bf, *ybf, *xbf, *ctxbf, *ffnbf, *wbf, *khh, *khl, *vth;
    cudaGetSymbolAddress((void**)&pe, g_pe);
    cudaGetSymbolAddress((void**)&x, g_x);
    cudaGetSymbolAddress((void**)&experts, g_experts);
    cudaGetSymbolAddress((void**)&summary, g_summary);
    cudaGetSymbolAddress((void**)&wgtp, g_wgt);
    cudaGetSymbolAddress((void**)&cntp, g_cnt);
    cudaGetSymbolAddress((void**)&listp, g_list);
    cudaGetSymbolAddress((void**)&qbf, g_qbf);
    cudaGetSymbolAddress((void**)&h1bf, g_h1bf);
    cudaGetSymbolAddress((void**)&ybf, g_ybf);
    cudaGetSymbolAddress((void**)&xbf, g_xbf);
    cudaGetSymbolAddress((void**)&ctxbf, g_ctxbf);
    cudaGetSymbolAddress((void**)&ffnbf, g_ffnbf);
    cudaGetSymbolAddress((void**)&wbf, g_wbf);
    cudaGetSymbolAddress((void**)&khh, g_khh);
    cudaGetSymbolAddress((void**)&khl, g_khl);
    cudaGetSymbolAddress((void**)&vth, g_vth);

    static int attr_set = 0;
    static cudaStream_t s2;
    static cudaEvent_t evFork, evW, evJoin;
    if (!attr_set) {
        cudaFuncSetAttribute(gemm2_kernel,
                             cudaFuncAttributeMaxDynamicSharedMemorySize, G2_SMEM);
        cudaFuncSetAttribute(attn_mma_kernel,
                             cudaFuncAttributeMaxDynamicSharedMemorySize, ATTN_SMEM);
        cudaStreamCreateWithFlags(&s2, cudaStreamNonBlocking);
        cudaEventCreateWithFlags(&evFork, cudaEventDisableTiming);
        cudaEventCreateWithFlags(&evW, cudaEventDisableTiming);
        cudaEventCreateWithFlags(&evJoin, cudaEventDisableTiming);
        attr_set = 1;
    }
    cudaStream_t s0 = 0;

    // --- fork immediately: s2 handles pe + weights + V chain ---
    cudaEventRecord(evFork, s0);
    cudaStreamWaitEvent(s2, evFork, 0);

    // s0: activation split (independent of s2 chain)
    conv_qraw_kernel<<<4096 * 768 / 256, 256, 0, s0>>>(q_raw, qbf);

    // s2: pe (+gate counter zero), all-weight conversion
    pe_kernel<<<S_, 256, 0, s2>>>(pe);
    {
        ConvSegs cs;
        cs.src[0] = exp_w1;  cs.dstOff[0] = W_EXPW1; cs.K[0] = 768;  cs.N[0] = 768;  cs.tOff[0] = 0;
        cs.src[1] = exp_w2;  cs.dstOff[1] = W_EXPW2; cs.K[1] = 768;  cs.N[1] = 512;  cs.tOff[1] = 2304;
        cs.src[2] = adapt_w; cs.dstOff[2] = W_ADAPT; cs.K[2] = 3072; cs.N[2] = 512;  cs.tOff[2] = 3840;
        cs.src[3] = kw;      cs.dstOff[3] = W_KW;    cs.K[3] = 512;  cs.N[3] = 512;  cs.tOff[3] = 5376;
        cs.src[4] = vw;      cs.dstOff[4] = W_VW;    cs.K[4] = 512;  cs.N[4] = 512;  cs.tOff[4] = 6400;
        cs.src[5] = ow;      cs.dstOff[5] = W_OW;    cs.K[5] = 512;  cs.N[5] = 512;  cs.tOff[5] = 7424;
        cs.src[6] = fw1;     cs.dstOff[6] = W_FW1;   cs.K[6] = 512;  cs.N[6] = 2048; cs.tOff[6] = 8448;
        cs.src[7] = fw2;     cs.dstOff[7] = W_FW2;   cs.K[7] = 2048; cs.N[7] = 512;  cs.tOff[7] = 12544;
        convB_all_kernel<<<16640, dim3(32, 8), 0, s2>>>(cs, wbf);
    }
    cudaEventRecord(evW, s2);     // pe + weights ready

    // s2 continues: y' = qa + pe, V for all layers -> transposed fp16
    add_pe_kernel<<<(int)(BSD / 256), 256, 0, s2>>>(qa, pe, ybf);
    gemmS(s2, ybf, 512, 1024, 0, wbf + W_VW, 512LL*512, 512, vb, D_, nullptr,
          nullptr, 0, nullptr, 0, nullptr, nullptr, vth,
          nullptr, nullptr, 0, 512, L_, 0);
    cudaEventRecord(evJoin, s2);

    // s0: MoE chain (needs qbf [s0] + wbf/pe [via evW])
    cudaStreamWaitEvent(s0, evW, 0);
    gemmS(s0, qbf, 3072, 6144, 0, wbf + W_ADAPT, 0, 3072, adapt_b, 0, nullptr,
          summary, 0, nullptr, 0, nullptr, nullptr, nullptr,
          nullptr, nullptr, 0, 512, 1, 1);
    gate_kernel<<<BS, 256, 0, s0>>>(summary, m_seq, gate_w, gate_b, wgtp, cntp, listp);
    gemmS(s0, qbf, 3072, 6144, 768, wbf + W_EXPW1, 768LL*768, 768, exp_b1, IN_, nullptr,
          nullptr, 0, h1bf, (long long)BS * 1536, nullptr, nullptr, nullptr,
          listp, cntp, 1, 768, NS_, 1);
    gemmS(s0, h1bf, 768, 1536, (long long)BS * 1536, wbf + W_EXPW2, 512LL*768, 768,
          exp_b2, D_, nullptr, experts, BSD, nullptr, 0,
          nullptr, nullptr, nullptr, listp, cntp, 2, 512, NS_, 0);
    moe_kernel<<<BS, 256, 0, s0>>>(wgtp, experts, moe_g, moe_b, pe, x, xbf);

    // --- join: layer loop needs vth (s2) and xbf (s0) ---
    cudaStreamWaitEvent(s0, evJoin, 0);

    for (int i = 0; i < L_; i++) {
        gemmS(s0, xbf, 512, 1024, 0, wbf + W_KW + (long long)i * 262144, 0, 512,
              kb + i*D_, 0, nullptr, nullptr, 0, nullptr, 0,
              khh, khl, nullptr, nullptr, nullptr, 0, 512, 1, 0);
        attn_mma_kernel<<<dim3(16, 32), 128, ATTN_SMEM, s0>>>(
            khh, khl, vth + (long long)i * 2097152, ctxbf);
        gemmS(s0, ctxbf, 512, 1024, 0, wbf + W_OW + (long long)i * 262144, 0, 512,
              ob + i*D_, 0, x, x, 0, nullptr, 0,
              nullptr, nullptr, nullptr, nullptr, nullptr, 0, 512, 1, 0);
        ln_kernel<<<BS, 256, 0, s0>>>(x, ln1g + i*D_, ln1b + i*D_, x, xbf);
        gemmS(s0, xbf, 512, 1024, 0, wbf + W_FW1 + (long long)i * 1048576, 0, 512,
              fb1 + i*FF_, 0, nullptr, nullptr, 0, ffnbf, 0,
              nullptr, nullptr, nullptr, nullptr, nullptr, 0, 2048, 1, 1);
        gemmS(s0, ffnbf, 2048, 4096, 0, wbf + W_FW2 + (long long)i * 1048576, 0, 2048,
              fb2 + i*D_, 0, x, x, 0, nullptr, 0,
              nullptr, nullptr, nullptr, nullptr, nullptr, 0, 512, 1, 0);
        ln_kernel<<<BS, 256, 0, s0>>>(x, ln2g + i*D_, ln2b + i*D_,
                               (i == L_-1) ? (float*)d_out : x,
                               (i == L_-1) ? nullptr : xbf);
    }
}